// round 1
// baseline (speedup 1.0000x reference)
#include <cuda_runtime.h>
#include <math.h>

// Per-batch learning-rate scale, computed by a tiny kernel into device-global
// scratch (no allocations allowed in kernel_launch).
__device__ float g_scale[128];

// scale[b] = 1 / (1024 + softplus(dot(x_b, eta_w) + eta_b))
__global__ void eta_scale_kernel(const float* __restrict__ x,
                                 const float* __restrict__ eta_w,
                                 const float* __restrict__ eta_b) {
    const int b = blockIdx.x;
    const float* xb = x + (size_t)b * 1024;

    float partial = 0.0f;
    for (int i = threadIdx.x; i < 1024; i += blockDim.x)
        partial += xb[i] * eta_w[i];

    // warp reduce
    for (int off = 16; off; off >>= 1)
        partial += __shfl_xor_sync(0xffffffffu, partial, off);

    __shared__ float red[8];
    const int warp = threadIdx.x >> 5;
    const int lane = threadIdx.x & 31;
    if (lane == 0) red[warp] = partial;
    __syncthreads();

    if (threadIdx.x == 0) {
        float s = 0.0f;
        const int nw = blockDim.x >> 5;
        for (int w = 0; w < nw; w++) s += red[w];
        const float z = s + eta_b[0];
        // numerically-stable softplus
        const float sp = fmaxf(z, 0.0f) + log1pf(expf(-fabsf(z)));
        g_scale[b] = 1.0f / (1024.0f + sp);
    }
}

// One warp per output row. Block = 256 threads = 8 rows of one batch.
// x_b staged in smem; W row held in registers between the dot and the write.
__global__ __launch_bounds__(256) void sm_update_kernel(
    const float* __restrict__ W,
    const float* __restrict__ x,
    const float* __restrict__ grad,
    float* __restrict__ out) {

    __shared__ float4 xs[256];  // x_b as 256 float4 = 1024 floats

    const int b = blockIdx.x >> 7;        // 128 blocks per batch (1024 rows / 8)
    const int ochunk = blockIdx.x & 127;
    const int t = threadIdx.x;
    const int warp = t >> 5;
    const int lane = t & 31;

    // stage x_b
    xs[t] = reinterpret_cast<const float4*>(x + (size_t)b * 1024)[t];
    __syncthreads();

    const int o = (ochunk << 3) + warp;
    const size_t row_off = ((size_t)b * 1024 + o) * 1024;
    const float4* wrow = reinterpret_cast<const float4*>(W + row_off);

    float4 wv[8];
    float dot = 0.0f;
#pragma unroll
    for (int k = 0; k < 8; k++) {
        const int idx = (k << 5) + lane;
        wv[k] = wrow[idx];
        const float4 xv = xs[idx];
        dot += wv[k].x * xv.x + wv[k].y * xv.y + wv[k].z * xv.z + wv[k].w * xv.w;
    }

    // warp-wide reduction of the row dot product
    for (int off = 16; off; off >>= 1)
        dot += __shfl_xor_sync(0xffffffffu, dot, off);

    const float err = dot - grad[(size_t)b * 1024 + o];
    const float se = g_scale[b] * err;

    float4* orow = reinterpret_cast<float4*>(out + row_off);
#pragma unroll
    for (int k = 0; k < 8; k++) {
        const int idx = (k << 5) + lane;
        const float4 xv = xs[idx];
        float4 r;
        r.x = wv[k].x - se * xv.x;
        r.y = wv[k].y - se * xv.y;
        r.z = wv[k].z - se * xv.z;
        r.w = wv[k].w - se * xv.w;
        orow[idx] = r;
    }
}

extern "C" void kernel_launch(void* const* d_in, const int* in_sizes, int n_in,
                              void* d_out, int out_size) {
    // metadata order: W_t [128,1024,1024], x_t [128,1024], grad_l_in [128,1024],
    //                 eta_w [1,1024], eta_b [1]
    const float* W     = (const float*)d_in[0];
    const float* x     = (const float*)d_in[1];
    const float* grad  = (const float*)d_in[2];
    const float* eta_w = (const float*)d_in[3];
    const float* eta_b = (const float*)d_in[4];
    float* out = (float*)d_out;

    eta_scale_kernel<<<128, 256>>>(x, eta_w, eta_b);
    sm_update_kernel<<<128 * 128, 256>>>(W, x, grad, out);
}

// round 2
// speedup vs baseline: 1.0130x; 1.0130x over previous
#include <cuda_runtime.h>
#include <math.h>

// Fully-fused Sherman–Morrison delta-rule update.
// out[b,o,:] = W[b,o,:] - scale_b * (W[b,o,:]·x_b - g[b,o]) * x_b
// scale_b = 1/(1024 + softplus(x_b·eta_w + eta_b))
//
// One warp per output row, 8 rows (one block) per 256 threads.
// scale_b is recomputed redundantly per block (eta_w is 4KB, L2-resident);
// the block reduction hides entirely under the W-row global-load latency.
__global__ __launch_bounds__(256) void sm_update_fused_kernel(
    const float* __restrict__ W,
    const float* __restrict__ x,
    const float* __restrict__ grad,
    const float* __restrict__ eta_w,
    const float* __restrict__ eta_b,
    float* __restrict__ out) {

    __shared__ float4 xs[256];   // x_b: 1024 floats
    __shared__ float red[8];
    __shared__ float s_scale;

    const int b = blockIdx.x >> 7;        // 128 blocks per batch
    const int ochunk = blockIdx.x & 127;
    const int t = threadIdx.x;
    const int warp = t >> 5;
    const int lane = t & 31;

    // stage x_b
    xs[t] = reinterpret_cast<const float4*>(x + (size_t)b * 1024)[t];
    __syncthreads();

    // --- eta partial: dot(x_b, eta_w), 4 elems/thread ---
    {
        const float4 ew = reinterpret_cast<const float4*>(eta_w)[t];
        const float4 xv = xs[t];
        float p = xv.x * ew.x + xv.y * ew.y + xv.z * ew.z + xv.w * ew.w;
        for (int off = 16; off; off >>= 1)
            p += __shfl_xor_sync(0xffffffffu, p, off);
        if (lane == 0) red[warp] = p;
    }

    // --- W row load + dot (the long-latency part; overlaps the reduction) ---
    const int o = (ochunk << 3) + warp;
    const size_t row_off = ((size_t)b * 1024 + o) * 1024;
    const float4* wrow = reinterpret_cast<const float4*>(W + row_off);

    float4 wv[8];
    float dot = 0.0f;
#pragma unroll
    for (int k = 0; k < 8; k++) {
        const int idx = (k << 5) + lane;
        wv[k] = __ldcs(wrow + idx);   // streaming: W read exactly once
        const float4 xv = xs[idx];
        dot += wv[k].x * xv.x + wv[k].y * xv.y + wv[k].z * xv.z + wv[k].w * xv.w;
    }
    for (int off = 16; off; off >>= 1)
        dot += __shfl_xor_sync(0xffffffffu, dot, off);

    // --- finish scale_b ---
    __syncthreads();               // red[] complete
    if (t == 0) {
        float s = red[0] + red[1] + red[2] + red[3]
                + red[4] + red[5] + red[6] + red[7];
        const float z = s + eta_b[0];
        const float sp = fmaxf(z, 0.0f) + log1pf(expf(-fabsf(z)));
        s_scale = 1.0f / (1024.0f + sp);
    }
    __syncthreads();               // s_scale visible

    const float err = dot - grad[(size_t)b * 1024 + o];
    const float se = s_scale * err;

    float4* orow = reinterpret_cast<float4*>(out + row_off);
#pragma unroll
    for (int k = 0; k < 8; k++) {
        const int idx = (k << 5) + lane;
        const float4 xv = xs[idx];
        float4 r;
        r.x = wv[k].x - se * xv.x;
        r.y = wv[k].y - se * xv.y;
        r.z = wv[k].z - se * xv.z;
        r.w = wv[k].w - se * xv.w;
        __stcs(orow + idx, r);     // streaming: out written exactly once
    }
}

extern "C" void kernel_launch(void* const* d_in, const int* in_sizes, int n_in,
                              void* d_out, int out_size) {
    // metadata order: W_t [128,1024,1024], x_t [128,1024], grad_l_in [128,1024],
    //                 eta_w [1,1024], eta_b [1]
    const float* W     = (const float*)d_in[0];
    const float* x     = (const float*)d_in[1];
    const float* grad  = (const float*)d_in[2];
    const float* eta_w = (const float*)d_in[3];
    const float* eta_b = (const float*)d_in[4];
    float* out = (float*)d_out;

    sm_update_fused_kernel<<<128 * 128, 256>>>(W, x, grad, eta_w, eta_b, out);
}